// round 4
// baseline (speedup 1.0000x reference)
#include <cuda_runtime.h>
#include <cuda_fp16.h>

// Causal MHA forward, fp16 tensor-core flash-attention, cp.async pipelined.
// Q/K/V: [2048, 2, 32, 64] fp32; out: [2048, 2, 2048] fp32. Causal mask analytic.

#define SQL 2048
#define ROWSTRIDE 4096
#define BM 128            // rows per CTA (8 warps x 16)
#define BN 64
#define HN 64
#define NT 256
#define LOG2E 1.4426950408889634f

__device__ __forceinline__ unsigned packh2(float lo, float hi) {
    __half2 h = __floats2half2_rn(lo, hi);
    return *(unsigned*)&h;
}

__device__ __forceinline__ float ex2(float x) {
    float y;
    asm("ex2.approx.f32 %0, %1;" : "=f"(y) : "f"(x));
    return y;
}

__device__ __forceinline__ void mma_f16(float c[4], const unsigned a[4],
                                        unsigned b0, unsigned b1) {
    asm volatile(
        "mma.sync.aligned.m16n8k16.row.col.f32.f16.f16.f32 "
        "{%0,%1,%2,%3}, {%4,%5,%6,%7}, {%8,%9}, {%0,%1,%2,%3};"
        : "+f"(c[0]), "+f"(c[1]), "+f"(c[2]), "+f"(c[3])
        : "r"(a[0]), "r"(a[1]), "r"(a[2]), "r"(a[3]), "r"(b0), "r"(b1));
}

__device__ __forceinline__ void ldsm4(unsigned& r0, unsigned& r1, unsigned& r2,
                                      unsigned& r3, unsigned addr) {
    asm volatile("ldmatrix.sync.aligned.m8n8.x4.shared.b16 {%0,%1,%2,%3}, [%4];"
                 : "=r"(r0), "=r"(r1), "=r"(r2), "=r"(r3) : "r"(addr));
}

__device__ __forceinline__ void ldsm4t(unsigned& r0, unsigned& r1, unsigned& r2,
                                       unsigned& r3, unsigned addr) {
    asm volatile("ldmatrix.sync.aligned.m8n8.x4.trans.shared.b16 {%0,%1,%2,%3}, [%4];"
                 : "=r"(r0), "=r"(r1), "=r"(r2), "=r"(r3) : "r"(addr));
}

__device__ __forceinline__ void cpa16(unsigned saddr, const float* g) {
    asm volatile("cp.async.cg.shared.global [%0], [%1], 16;"
                 :: "r"(saddr), "l"(g));
}

__global__ __launch_bounds__(NT, 2)
void attn_fwd_h(const float* __restrict__ Q,
                const float* __restrict__ K,
                const float* __restrict__ V,
                float* __restrict__ Out)
{
    __shared__ __align__(16) float  stK[BN * HN];   // fp32 staging (cp.async dst)
    __shared__ __align__(16) float  stV[BN * HN];
    __shared__ __align__(16) __half sK[BN * HN];    // fp16 swizzled MMA tiles
    __shared__ __align__(16) __half sV[BN * HN];    // total smem = 48 KB exactly

    const int t    = threadIdx.x;
    const int lane = t & 31;
    const int w    = t >> 5;
    const int g    = lane >> 2;
    const int tg   = lane & 3;

    const int qt    = (int)gridDim.x - 1 - (int)blockIdx.x;  // heavy tiles first
    const int base  = (int)blockIdx.y * HN;
    const int qrow0 = qt * BM;
    const int iA    = w * 16 + g;
    const int iB    = iA + 8;

    const unsigned sKb  = (unsigned)__cvta_generic_to_shared(sK);
    const unsigned sVb  = (unsigned)__cvta_generic_to_shared(sV);
    const unsigned stKb = (unsigned)__cvta_generic_to_shared(stK);
    const unsigned stVb = (unsigned)__cvta_generic_to_shared(stV);

    // ---- per-thread cp.async addressing: 2 (K/V) x 2 passes x 2 chunks ----
    const int cj = t >> 3;                 // row 0..31 (pass adds +32)
    const int cc = (t & 7) * 8;            // float col 0..56 step 8

    // ---- issue tile-0 staging loads first (overlap with Q fragment LDGs) ----
    {
        const float* kg = K + cj * ROWSTRIDE + base + cc;
        const float* vg = V + cj * ROWSTRIDE + base + cc;
        unsigned so = (unsigned)(cj * HN + cc) * 4u;
        cpa16(stKb + so,        kg);
        cpa16(stKb + so + 16u,  kg + 4);
        cpa16(stVb + so,        vg);
        cpa16(stVb + so + 16u,  vg + 4);
        kg += 32 * ROWSTRIDE; vg += 32 * ROWSTRIDE; so += 32u * HN * 4u;
        cpa16(stKb + so,        kg);
        cpa16(stKb + so + 16u,  kg + 4);
        cpa16(stVb + so,        vg);
        cpa16(stVb + so + 16u,  vg + 4);
        asm volatile("cp.async.commit_group;");
    }

    // ---- Q fragments, pre-scaled by 0.125*log2(e) (exp -> ex2 domain) ----
    unsigned qa[4][4];
    {
        const float SC = 0.125f * LOG2E;
        const float* qp = Q + (qrow0 + iA) * ROWSTRIDE + base;
        #pragma unroll
        for (int kc = 0; kc < 4; ++kc) {
            float2 x0 = *(const float2*)(qp + kc * 16 + 2 * tg);
            float2 x1 = *(const float2*)(qp + 8 * ROWSTRIDE + kc * 16 + 2 * tg);
            float2 x2 = *(const float2*)(qp + kc * 16 + 2 * tg + 8);
            float2 x3 = *(const float2*)(qp + 8 * ROWSTRIDE + kc * 16 + 2 * tg + 8);
            qa[kc][0] = packh2(SC * x0.x, SC * x0.y);
            qa[kc][1] = packh2(SC * x1.x, SC * x1.y);
            qa[kc][2] = packh2(SC * x2.x, SC * x2.y);
            qa[kc][3] = packh2(SC * x3.x, SC * x3.y);
        }
    }

    float mA = -1e30f, mB = -1e30f, lA = 0.f, lB = 0.f;
    float oacc[8][4];
    #pragma unroll
    for (int nt = 0; nt < 8; ++nt)
        #pragma unroll
        for (int r = 0; r < 4; ++r) oacc[nt][r] = 0.f;

    const int ktmax = 2 * qt + 1;
    for (int kt = 0; kt <= ktmax; ++kt) {
        asm volatile("cp.async.wait_group 0;");
        __syncthreads();   // staging complete; prev GEMM2 done with sK/sV

        // ---- convert staging fp32 -> swizzled fp16 (conflict-free LDS/STS) ----
        #pragma unroll
        for (int p = 0; p < 4; ++p) {
            int f4 = t + p * NT;           // 0..1023
            int f  = f4 * 4;
            int j  = f >> 6;
            int h0 = f & 63;
            int dst = j * 64 + (((h0 >> 3) ^ (j & 7)) << 3) + (h0 & 7);
            float4 kx = *(const float4*)&stK[f];
            float4 vx = *(const float4*)&stV[f];
            uint2 ks; ks.x = packh2(kx.x, kx.y); ks.y = packh2(kx.z, kx.w);
            uint2 vs; vs.x = packh2(vx.x, vx.y); vs.y = packh2(vx.z, vx.w);
            *(uint2*)&sK[dst] = ks;
            *(uint2*)&sV[dst] = vs;
        }
        __syncthreads();   // fp16 ready; staging fully consumed

        // ---- kick off next tile's staging loads (hidden under the GEMMs) ----
        if (kt < ktmax) {
            const int nrow0 = (kt + 1) * BN;
            const float* kg = K + (nrow0 + cj) * ROWSTRIDE + base + cc;
            const float* vg = V + (nrow0 + cj) * ROWSTRIDE + base + cc;
            unsigned so = (unsigned)(cj * HN + cc) * 4u;
            cpa16(stKb + so,        kg);
            cpa16(stKb + so + 16u,  kg + 4);
            cpa16(stVb + so,        vg);
            cpa16(stVb + so + 16u,  vg + 4);
            kg += 32 * ROWSTRIDE; vg += 32 * ROWSTRIDE; so += 32u * HN * 4u;
            cpa16(stKb + so,        kg);
            cpa16(stKb + so + 16u,  kg + 4);
            cpa16(stVb + so,        vg);
            cpa16(stVb + so + 16u,  vg + 4);
            asm volatile("cp.async.commit_group;");
        }

        // ---- GEMM1: S = Q K^T (log2 domain) ----
        float sacc[8][4];
        #pragma unroll
        for (int nt = 0; nt < 8; ++nt)
            #pragma unroll
            for (int r = 0; r < 4; ++r) sacc[nt][r] = 0.f;

        #pragma unroll
        for (int hg = 0; hg < 2; ++hg) {
            #pragma unroll
            for (int nt = 0; nt < 8; ++nt) {
                int m = lane >> 3, r = lane & 7;
                int j = nt * 8 + r;
                unsigned addr = sKb +
                    (unsigned)(j * 64 + (((hg * 4 + m) ^ (j & 7)) << 3)) * 2u;
                unsigned r0, r1, r2, r3;
                ldsm4(r0, r1, r2, r3, addr);
                mma_f16(sacc[nt], qa[hg * 2],     r0, r1);
                mma_f16(sacc[nt], qa[hg * 2 + 1], r2, r3);
            }
        }

        // ---- causal mask (diagonal super-tile only) ----
        if (kt >= 2 * qt) {
            const int krow0 = kt * BN;
            const int igA = qrow0 + iA, igB = qrow0 + iB;
            #pragma unroll
            for (int nt = 0; nt < 8; ++nt) {
                int c0 = krow0 + nt * 8 + 2 * tg;
                if (c0     > igA) sacc[nt][0] = -1e30f;
                if (c0 + 1 > igA) sacc[nt][1] = -1e30f;
                if (c0     > igB) sacc[nt][2] = -1e30f;
                if (c0 + 1 > igB) sacc[nt][3] = -1e30f;
            }
        }

        // ---- online softmax (log2 domain, register/shfl only) ----
        float rmA = -1e30f, rmB = -1e30f;
        #pragma unroll
        for (int nt = 0; nt < 8; ++nt) {
            rmA = fmaxf(rmA, fmaxf(sacc[nt][0], sacc[nt][1]));
            rmB = fmaxf(rmB, fmaxf(sacc[nt][2], sacc[nt][3]));
        }
        rmA = fmaxf(rmA, __shfl_xor_sync(0xffffffffu, rmA, 1));
        rmA = fmaxf(rmA, __shfl_xor_sync(0xffffffffu, rmA, 2));
        rmB = fmaxf(rmB, __shfl_xor_sync(0xffffffffu, rmB, 1));
        rmB = fmaxf(rmB, __shfl_xor_sync(0xffffffffu, rmB, 2));
        const float mnA = fmaxf(mA, rmA), mnB = fmaxf(mB, rmB);
        const float scA = ex2(mA - mnA), scB = ex2(mB - mnB);

        float rsA = 0.f, rsB = 0.f;
        #pragma unroll
        for (int nt = 0; nt < 8; ++nt) {
            sacc[nt][0] = ex2(sacc[nt][0] - mnA);
            sacc[nt][1] = ex2(sacc[nt][1] - mnA);
            sacc[nt][2] = ex2(sacc[nt][2] - mnB);
            sacc[nt][3] = ex2(sacc[nt][3] - mnB);
            rsA += sacc[nt][0] + sacc[nt][1];
            rsB += sacc[nt][2] + sacc[nt][3];
        }
        rsA += __shfl_xor_sync(0xffffffffu, rsA, 1);
        rsA += __shfl_xor_sync(0xffffffffu, rsA, 2);
        rsB += __shfl_xor_sync(0xffffffffu, rsB, 1);
        rsB += __shfl_xor_sync(0xffffffffu, rsB, 2);
        lA = lA * scA + rsA;  mA = mnA;
        lB = lB * scB + rsB;  mB = mnB;
        #pragma unroll
        for (int nt = 0; nt < 8; ++nt) {
            oacc[nt][0] *= scA; oacc[nt][1] *= scA;
            oacc[nt][2] *= scB; oacc[nt][3] *= scB;
        }

        // ---- pack P fragments (C-layout == A-layout; no smem round trip) ----
        unsigned pa[4][4];
        #pragma unroll
        for (int kc = 0; kc < 4; ++kc) {
            pa[kc][0] = packh2(sacc[2 * kc][0],     sacc[2 * kc][1]);
            pa[kc][1] = packh2(sacc[2 * kc][2],     sacc[2 * kc][3]);
            pa[kc][2] = packh2(sacc[2 * kc + 1][0], sacc[2 * kc + 1][1]);
            pa[kc][3] = packh2(sacc[2 * kc + 1][2], sacc[2 * kc + 1][3]);
        }

        // ---- GEMM2: O += P V via ldmatrix.trans ----
        #pragma unroll
        for (int kc = 0; kc < 4; ++kc) {
            #pragma unroll
            for (int ntp = 0; ntp < 4; ++ntp) {
                int m = lane >> 3, r = lane & 7;
                int j  = kc * 16 + (m & 1) * 8 + r;
                int hc = 2 * ntp + (m >> 1);
                unsigned addr = sVb +
                    (unsigned)(j * 64 + ((hc ^ (j & 7)) << 3)) * 2u;
                unsigned r0, r1, r2, r3;
                ldsm4t(r0, r1, r2, r3, addr);
                mma_f16(oacc[2 * ntp],     pa[kc], r0, r1);
                mma_f16(oacc[2 * ntp + 1], pa[kc], r2, r3);
            }
        }
    }

    // ---- epilogue: normalize + store ----
    const float ivA = 1.f / lA, ivB = 1.f / lB;
    float* oA = Out + (qrow0 + iA) * ROWSTRIDE + base + 2 * tg;
    float* oB = Out + (qrow0 + iB) * ROWSTRIDE + base + 2 * tg;
    #pragma unroll
    for (int nt = 0; nt < 8; ++nt) {
        float2 a; a.x = oacc[nt][0] * ivA; a.y = oacc[nt][1] * ivA;
        float2 b; b.x = oacc[nt][2] * ivB; b.y = oacc[nt][3] * ivB;
        *(float2*)(oA + nt * 8) = a;
        *(float2*)(oB + nt * 8) = b;
    }
}

extern "C" void kernel_launch(void* const* d_in, const int* in_sizes, int n_in,
                              void* d_out, int out_size)
{
    const float* q = (const float*)d_in[0];
    const float* k = (const float*)d_in[1];
    const float* v = (const float*)d_in[2];
    // d_in[3] = attention_mask (causal) — analytic in-kernel.
    float* out = (float*)d_out;

    dim3 grid(SQL / BM, 2 * 32);
    attn_fwd_h<<<grid, NT>>>(q, k, v, out);
}